// round 12
// baseline (speedup 1.0000x reference)
#include <cuda_runtime.h>

#define NMAX 100000
#define EMAX 3300000
#define DD 128

// Static device scratch (allocation-free). 16B-aligned for vector ld/st.
__device__ __align__(16) float g_bufA[NMAX * DD];
__device__ __align__(16) float g_bufB[NMAX * DD];
__device__ __align__(16) float g_dinv[NMAX];
__device__ int   g_deg[NMAX];
__device__ int   g_fill[NMAX];
__device__ int   g_rowptr[NMAX + 1];
__device__ int   g_bsum[256];
__device__ int   g_bsum2[256];
__device__ int   g_csrsrc[EMAX];
__device__ int   g_is64;
// transposed weights: WT[c][k]
__device__ __align__(16) float g_WdT[32 * 768];
__device__ __align__(16) float g_WtT[32 * 768];
__device__ __align__(16) float g_WinT[128 * 128];
__device__ __align__(16) float g_Wg1T[128 * 128];
__device__ __align__(16) float g_Wg2T[128 * 128];
__device__ __align__(16) float g_Wo1T[128 * 128];

__device__ __forceinline__ float lrelu(float v) { return v > 0.0f ? v : 0.01f * v; }

// packed f32x2 fma: d = a*b + d  (two independent fp32 FMAs, 2x FFMA rate)
__device__ __forceinline__ void ffma2(unsigned long long& d, unsigned long long a, unsigned long long b) {
    asm("fma.rn.f32x2 %0, %1, %2, %0;" : "+l"(d) : "l"(a), "l"(b));
}
__device__ __forceinline__ float f2sum(unsigned long long v) {
    return __int_as_float((int)(v & 0xffffffffull)) + __int_as_float((int)(v >> 32));
}
__device__ __forceinline__ unsigned long long ld64(const float* p) {
    return *(const unsigned long long*)p;
}

// Edge index fetch robust to int32-vs-int64 delivery of edge_index.
__device__ __forceinline__ int edge_at(const void* eidx, long long pos) {
    if (g_is64) return (int)(((const long long*)eidx)[pos]);
    return ((const int*)eidx)[pos];
}

__global__ void sniff_dtype(const int* __restrict__ p, int n) {
    if (threadIdx.x == 0 && blockIdx.x == 0) {
        int is64 = 1;
        for (int i = 0; i < 64; i++) {
            int lo = p[2 * i], hi = p[2 * i + 1];
            if (hi != 0 || lo < 0 || lo >= n) { is64 = 0; break; }
        }
        g_is64 = is64;
    }
}

// ---------------- weight transposes (one launch) ----------------
__global__ void transpose_all(
    const float* __restrict__ Wd, const float* __restrict__ Wt,
    const float* __restrict__ Win, const float* __restrict__ Wg1,
    const float* __restrict__ Wg2, const float* __restrict__ Wo1)
{
    int i = blockIdx.x * blockDim.x + threadIdx.x;
    if (i < 24576) { int r = i >> 5, c = i & 31; g_WdT[c * 768 + r] = Wd[i]; return; }
    i -= 24576;
    if (i < 24576) { int r = i >> 5, c = i & 31; g_WtT[c * 768 + r] = Wt[i]; return; }
    i -= 24576;
    if (i < 16384) { int r = i >> 7, c = i & 127; g_WinT[c * 128 + r] = Win[i]; return; }
    i -= 16384;
    if (i < 16384) { int r = i >> 7, c = i & 127; g_Wg1T[c * 128 + r] = Wg1[i]; return; }
    i -= 16384;
    if (i < 16384) { int r = i >> 7, c = i & 127; g_Wg2T[c * 128 + r] = Wg2[i]; return; }
    i -= 16384;
    if (i < 16384) { int r = i >> 7, c = i & 127; g_Wo1T[c * 128 + r] = Wo1[i]; return; }
}

// ---------------- degree ----------------
__global__ void deg_zero(int n) {
    int i = blockIdx.x * blockDim.x + threadIdx.x;
    if (i < n) { g_deg[i] = 0; g_fill[i] = 0; }
}
__global__ void deg_count(const void* __restrict__ eidx, int ne) {
    int e = blockIdx.x * blockDim.x + threadIdx.x;
    if (e < ne) atomicAdd(&g_deg[edge_at(eidx, (long long)ne + e)], 1);
}
__global__ void deg_finish(int n) {
    int i = blockIdx.x * blockDim.x + threadIdx.x;
    if (i < n) g_dinv[i] = rsqrtf((float)(g_deg[i] + 1));
}

// ---------------- exclusive scan of g_deg -> g_rowptr ----------------
__global__ void __launch_bounds__(256) scan1(int n) {
    __shared__ int warpsum[8];
    int t = threadIdx.x;
    int i0 = blockIdx.x * 1024 + t * 4;
    int v0 = (i0 + 0 < n) ? g_deg[i0 + 0] : 0;
    int v1 = (i0 + 1 < n) ? g_deg[i0 + 1] : 0;
    int v2 = (i0 + 2 < n) ? g_deg[i0 + 2] : 0;
    int v3 = (i0 + 3 < n) ? g_deg[i0 + 3] : 0;
    int tsum = v0 + v1 + v2 + v3;
    int x = tsum;
    #pragma unroll
    for (int o = 1; o < 32; o <<= 1) {
        int y = __shfl_up_sync(0xffffffffu, x, o);
        if ((t & 31) >= o) x += y;
    }
    if ((t & 31) == 31) warpsum[t >> 5] = x;
    __syncthreads();
    if (t < 32) {
        int w = (t < 8) ? warpsum[t] : 0;
        int xx = w;
        #pragma unroll
        for (int o = 1; o < 8; o <<= 1) {
            int y = __shfl_up_sync(0xffffffffu, xx, o);
            if (t >= o) xx += y;
        }
        if (t < 8) warpsum[t] = xx - w;
    }
    __syncthreads();
    int ex = x - tsum + warpsum[t >> 5];
    if (i0 + 0 < n) g_rowptr[i0 + 0] = ex;
    if (i0 + 1 < n) g_rowptr[i0 + 1] = ex + v0;
    if (i0 + 2 < n) g_rowptr[i0 + 2] = ex + v0 + v1;
    if (i0 + 3 < n) g_rowptr[i0 + 3] = ex + v0 + v1 + v2;
    if (t == 255) g_bsum[blockIdx.x] = ex + tsum;
}
__global__ void __launch_bounds__(128) scan2(int nb) {
    __shared__ int ws[4];
    int t = threadIdx.x;
    int v = (t < nb) ? g_bsum[t] : 0;
    int x = v;
    #pragma unroll
    for (int o = 1; o < 32; o <<= 1) {
        int y = __shfl_up_sync(0xffffffffu, x, o);
        if ((t & 31) >= o) x += y;
    }
    if ((t & 31) == 31) ws[t >> 5] = x;
    __syncthreads();
    if (t < 32) {
        int w = (t < 4) ? ws[t] : 0;
        int xx = w;
        #pragma unroll
        for (int o = 1; o < 4; o <<= 1) {
            int y = __shfl_up_sync(0xffffffffu, xx, o);
            if (t >= o) xx += y;
        }
        if (t < 4) ws[t] = xx - w;
    }
    __syncthreads();
    g_bsum2[t] = x - v + ws[t >> 5];
}
__global__ void __launch_bounds__(256) scan3(int n, int ne) {
    int t = threadIdx.x;
    int add = g_bsum2[blockIdx.x];
    int i0 = blockIdx.x * 1024 + t * 4;
    #pragma unroll
    for (int j = 0; j < 4; j++)
        if (i0 + j < n) g_rowptr[i0 + j] += add;
    if (blockIdx.x == 0 && t == 0) g_rowptr[n] = ne;
}

__global__ void csr_fill(const void* __restrict__ eidx, int ne) {
    int e = blockIdx.x * blockDim.x + threadIdx.x;
    if (e >= ne) return;
    int s = edge_at(eidx, e);
    int d = edge_at(eidx, (long long)ne + e);
    int pos = g_rowptr[d] + atomicAdd(&g_fill[d], 1);
    g_csrsrc[pos] = s;
}

// ---------------- fused feature kernel (f32x2, 128-k chunks -> 4 CTAs/SM) ----------------
#define KF_NB 32
#define KF_CH 128          // k-chunk
#define KF_SX 132          // row stride (128 + 4 pad); 132%32=4 -> conflict-free, rows 16B-aligned
#define KF_SW 132
#define X0S   134          // x0 row stride; 134%32=6 -> conflict-free
#define SREDP 33
#define KF_SMEM ((KF_NB * KF_SX + 32 * KF_SW + KF_NB * X0S) * 4)   // ~50.9 KB -> 4 CTAs/SM

__global__ void __launch_bounds__(256, 4) kfeat(
    const float* __restrict__ des, const float* __restrict__ tweet,
    const float* __restrict__ nump, const float* __restrict__ catp,
    const float* __restrict__ bd, const float* __restrict__ bt,
    const float* __restrict__ bn, const float* __restrict__ bc,
    const float* __restrict__ Wn, const float* __restrict__ Wc,
    const float* __restrict__ bin, int n)
{
    extern __shared__ float smem[];
    float* sx   = smem;                      // [32][132]
    float* sw   = sx + KF_NB * KF_SX;        // [32][132]
    float* x0   = sw + 32 * KF_SW;           // [32][134]
    float* sred = sw;                        // overlay: [4][32][33] = 4224 floats == 32*132

    int t = threadIdx.x;
    int node0 = blockIdx.x * KF_NB;
    int ks = t >> 6;          // k-slice 0..3
    int cg = (t >> 3) & 7;    // col group (4 cols)
    int ng = t & 7;           // node group (nodes ng+8j)
    int c0 = cg * 4;

    // ---- phase A: des/tweet 768->32 GEMMs ----
    for (int side = 0; side < 2; side++) {
        const float* X  = side ? tweet : des;
        const float* WT = side ? g_WtT : g_WdT;
        unsigned long long acc[4][4];
        #pragma unroll
        for (int i = 0; i < 4; i++)
            #pragma unroll
            for (int j = 0; j < 4; j++) acc[i][j] = 0;

        for (int chunk = 0; chunk < 6; chunk++) {
            int k0 = chunk * KF_CH;
            __syncthreads();
            // stage sx: 32 nodes x 128 k (32 float4 per node)
            for (int i2 = t; i2 < KF_NB * 32; i2 += 256) {
                int m = i2 >> 5, q = i2 & 31;
                int row = min(node0 + m, n - 1);
                float4 v = ((const float4*)(X + (size_t)row * 768 + k0))[q];
                *(float4*)(sx + m * KF_SX + 4 * q) = v;
            }
            // stage sw: 32 cols x 128 k
            for (int i2 = t; i2 < 32 * 32; i2 += 256) {
                int c = i2 >> 5, q = i2 & 31;
                float4 v = ((const float4*)(WT + c * 768 + k0))[q];
                *(float4*)(sw + c * KF_SW + 4 * q) = v;
            }
            __syncthreads();

            int kb = ks * 32;  // this slice's 32-k window within chunk
            #pragma unroll 4
            for (int kk = 0; kk < 16; kk++) {
                int k = kb + 2 * kk;
                unsigned long long x2[4], w2[4];
                #pragma unroll
                for (int j = 0; j < 4; j++) x2[j] = ld64(sx + (ng + 8 * j) * KF_SX + k);
                #pragma unroll
                for (int i = 0; i < 4; i++) w2[i] = ld64(sw + (c0 + i) * KF_SW + k);
                #pragma unroll
                for (int i = 0; i < 4; i++)
                    #pragma unroll
                    for (int j = 0; j < 4; j++) ffma2(acc[i][j], x2[j], w2[i]);
            }
        }
        // cross-slice reduction (sred overlays sw)
        __syncthreads();
        #pragma unroll
        for (int i = 0; i < 4; i++)
            #pragma unroll
            for (int j = 0; j < 4; j++)
                sred[ks * (KF_NB * SREDP) + (ng + 8 * j) * SREDP + c0 + i] = f2sum(acc[i][j]);
        __syncthreads();
        const float* bias = side ? bt : bd;
        for (int o = t; o < KF_NB * 32; o += 256) {
            int node = o >> 5, col = o & 31;
            float v = sred[node * SREDP + col]
                    + sred[KF_NB * SREDP + node * SREDP + col]
                    + sred[2 * KF_NB * SREDP + node * SREDP + col]
                    + sred[3 * KF_NB * SREDP + node * SREDP + col]
                    + bias[col];
            x0[node * X0S + side * 32 + col] = lrelu(v);
        }
    }

    // ---- num/cat features: cols 64..127 ----
    for (int o = t; o < KF_NB * 64; o += 256) {
        int m = o >> 6, c = o & 63;
        int row = min(node0 + m, n - 1);
        float v;
        if (c < 32) {
            v = bn[c];
            const float* xp = nump + (size_t)row * 6;
            #pragma unroll
            for (int k = 0; k < 6; k++) v += xp[k] * Wn[k * 32 + c];
        } else {
            int cc = c - 32;
            v = bc[cc];
            const float* xp = catp + (size_t)row * 11;
            #pragma unroll
            for (int k = 0; k < 11; k++) v += xp[k] * Wc[k * 32 + cc];
        }
        x0[m * X0S + 64 + c] = lrelu(v);
    }
    __syncthreads();

    // ---- phase B: x1 = lrelu(x0 @ Win + bin) -> g_bufA ----
    {
        int cg2 = t >> 3;   // 0..31 -> cols cg2*4..+3
        int ng2 = t & 7;    // nodes ng2 + 8j
        int cb0 = cg2 * 4;
        unsigned long long acc[4][4];
        #pragma unroll
        for (int i = 0; i < 4; i++)
            #pragma unroll
            for (int j = 0; j < 4; j++) acc[i][j] = 0;

        #pragma unroll 4
        for (int kk = 0; kk < 64; kk++) {
            int k = 2 * kk;
            unsigned long long x2[4];
            #pragma unroll
            for (int j = 0; j < 4; j++) x2[j] = ld64(x0 + (ng2 + 8 * j) * X0S + k);
            #pragma unroll
            for (int i = 0; i < 4; i++) {
                unsigned long long w2 = ld64(g_WinT + (cb0 + i) * 128 + k);
                #pragma unroll
                for (int j = 0; j < 4; j++) ffma2(acc[i][j], x2[j], w2);
            }
        }
        #pragma unroll
        for (int i = 0; i < 4; i++) {
            float b = bin[cb0 + i];
            #pragma unroll
            for (int j = 0; j < 4; j++) {
                int node = node0 + ng2 + 8 * j;
                if (node < n)
                    g_bufA[(size_t)node * 128 + cb0 + i] = lrelu(f2sum(acc[i][j]) + b);
            }
        }
    }
}

// ---------------- 128x128 GEMM (f32x2): g_bufA @ W -> g_bufB, 32 nodes/block ----------------
__global__ void __launch_bounds__(256) gemm128(int sel, int n)
{
    __shared__ float xs[32 * X0S];
    const float* WT = sel ? g_Wg2T : g_Wg1T;
    int t = threadIdx.x;
    int node0 = blockIdx.x * 32;

    for (int i = t; i < 32 * 64; i += 256) {
        int m = i >> 6, q = i & 63;
        int row = min(node0 + m, n - 1);
        float2 v = ((const float2*)(g_bufA + (size_t)row * 128))[q];
        *(float2*)(xs + m * X0S + 2 * q) = v;
    }
    __syncthreads();

    int cg = t >> 3;   // 0..31 -> cols cg*4..+3
    int ng = t & 7;    // nodes ng + 8j, j=0..3
    int c0 = cg * 4;
    unsigned long long acc[4][4];
    #pragma unroll
    for (int i = 0; i < 4; i++)
        #pragma unroll
        for (int j = 0; j < 4; j++) acc[i][j] = 0;

    #pragma unroll 4
    for (int kk = 0; kk < 64; kk++) {
        int k = 2 * kk;
        unsigned long long x2[4];
        #pragma unroll
        for (int j = 0; j < 4; j++) x2[j] = ld64(xs + (ng + 8 * j) * X0S + k);
        #pragma unroll
        for (int i = 0; i < 4; i++) {
            unsigned long long w2 = ld64(WT + (c0 + i) * 128 + k);
            #pragma unroll
            for (int j = 0; j < 4; j++) ffma2(acc[i][j], x2[j], w2);
        }
    }
    #pragma unroll
    for (int i = 0; i < 4; i++)
        #pragma unroll
        for (int j = 0; j < 4; j++) {
            int node = node0 + ng + 8 * j;
            if (node < n)
                g_bufB[(size_t)node * 128 + c0 + i] = f2sum(acc[i][j]);
        }
}

// ---------------- CSR gather aggregation (fused self-loop + bias) ----------------
__global__ void __launch_bounds__(256) gather(const float* __restrict__ bias, int n)
{
    int gid = blockIdx.x * blockDim.x + threadIdx.x;
    int node = gid >> 5;
    int lane = gid & 31;
    if (node >= n) return;

    const float4* Y4 = (const float4*)g_bufB;
    float wd = g_dinv[node];
    float4 y = Y4[(size_t)node * 32 + lane];
    float4 acc, acc2;
    acc.x = wd * y.x; acc.y = wd * y.y; acc.z = wd * y.z; acc.w = wd * y.w;
    acc2.x = 0.f; acc2.y = 0.f; acc2.z = 0.f; acc2.w = 0.f;

    int lo = g_rowptr[node], hi = g_rowptr[node + 1];
    int e = lo;
    for (; e + 2 <= hi; e += 2) {
        int s0 = g_csrsrc[e], s1 = g_csrsrc[e + 1];
        float w0 = g_dinv[s0], w1 = g_dinv[s1];
        float4 a4 = Y4[(size_t)s0 * 32 + lane];
        float4 b4 = Y4[(size_t)s1 * 32 + lane];
        acc.x += w0 * a4.x; acc.y += w0 * a4.y; acc.z += w0 * a4.z; acc.w += w0 * a4.w;
        acc2.x += w1 * b4.x; acc2.y += w1 * b4.y; acc2.z += w1 * b4.z; acc2.w += w1 * b4.w;
    }
    if (e < hi) {
        int s = g_csrsrc[e];
        float w = g_dinv[s];
        float4 ys = Y4[(size_t)s * 32 + lane];
        acc.x += w * ys.x; acc.y += w * ys.y; acc.z += w * ys.z; acc.w += w * ys.w;
    }
    acc.x += acc2.x; acc.y += acc2.y; acc.z += acc2.z; acc.w += acc2.w;

    float4 b4 = ((const float4*)bias)[lane];
    float4 o;
    o.x = wd * acc.x + b4.x; o.y = wd * acc.y + b4.y;
    o.z = wd * acc.z + b4.z; o.w = wd * acc.w + b4.w;
    ((float4*)g_bufA)[(size_t)node * 32 + lane] = o;
}

// ---------------- output head (f32x2 phase1): 32 nodes/block ----------------
__global__ void __launch_bounds__(256) kout(
    const float* __restrict__ bo1,
    const float* __restrict__ Wo2, const float* __restrict__ bo2,
    float* __restrict__ out, int n)
{
    __shared__ float xs[32 * X0S];
    __shared__ float sa[32 * X0S];
    int t = threadIdx.x;
    int node0 = blockIdx.x * 32;

    for (int i = t; i < 32 * 64; i += 256) {
        int m = i >> 6, q = i & 63;
        int row = min(node0 + m, n - 1);
        float2 v = ((const float2*)(g_bufA + (size_t)row * 128))[q];
        *(float2*)(xs + m * X0S + 2 * q) = v;
    }
    __syncthreads();

    int cg = t >> 3;
    int ng = t & 7;
    int c0 = cg * 4;
    unsigned long long acc[4][4];
    #pragma unroll
    for (int i = 0; i < 4; i++)
        #pragma unroll
        for (int j = 0; j < 4; j++) acc[i][j] = 0;

    #pragma unroll 4
    for (int kk = 0; kk < 64; kk++) {
        int k = 2 * kk;
        unsigned long long x2[4];
        #pragma unroll
        for (int j = 0; j < 4; j++) x2[j] = ld64(xs + (ng + 8 * j) * X0S + k);
        #pragma unroll
        for (int i = 0; i < 4; i++) {
            unsigned long long w2 = ld64(g_Wo1T + (c0 + i) * 128 + k);
            #pragma unroll
            for (int j = 0; j < 4; j++) ffma2(acc[i][j], x2[j], w2);
        }
    }
    #pragma unroll
    for (int i = 0; i < 4; i++) {
        float b = bo1[c0 + i];
        #pragma unroll
        for (int j = 0; j < 4; j++)
            sa[(ng + 8 * j) * X0S + c0 + i] = lrelu(f2sum(acc[i][j]) + b);
    }
    __syncthreads();

    // final 128->2 projection: 64 threads, one (node, class) each
    if (t < 64) {
        int m = t >> 1, c = t & 1;
        float s = bo2[c];
        const float* row = sa + m * X0S;
        #pragma unroll 4
        for (int k = 0; k < 128; k++) s += row[k] * Wo2[k * 2 + c];
        int node = node0 + m;
        if (node < n) out[(size_t)node * 2 + c] = s;
    }
}

extern "C" void kernel_launch(void* const* d_in, const int* in_sizes, int n_in,
                              void* d_out, int out_size)
{
    const float* des   = (const float*)d_in[0];
    const float* tweet = (const float*)d_in[1];
    const float* nump  = (const float*)d_in[2];
    const float* catp  = (const float*)d_in[3];
    const void*  eidx  = d_in[4];
    const float* Wd  = (const float*)d_in[6];  const float* bd  = (const float*)d_in[7];
    const float* Wt  = (const float*)d_in[8];  const float* bt  = (const float*)d_in[9];
    const float* Wn  = (const float*)d_in[10]; const float* bn  = (const float*)d_in[11];
    const float* Wc  = (const float*)d_in[12]; const float* bc  = (const float*)d_in[13];
    const float* Win = (const float*)d_in[14]; const float* bin = (const float*)d_in[15];
    const float* Wg1 = (const float*)d_in[16]; const float* bg1 = (const float*)d_in[17];
    const float* Wg2 = (const float*)d_in[18]; const float* bg2 = (const float*)d_in[19];
    const float* Wo1 = (const float*)d_in[20]; const float* bo1 = (const float*)d_in[21];
    const float* Wo2 = (const float*)d_in[22]; const float* bo2 = (const float*)d_in[23];
    float* out = (float*)d_out;

    int n  = in_sizes[2] / 6;
    int ne = in_sizes[5];
    int nb = (n + 1023) / 1024;

    cudaFuncSetAttribute(kfeat, cudaFuncAttributeMaxDynamicSharedMemorySize, KF_SMEM);

    // kfeat stays at launch slot #4 (the profiled launch).
    sniff_dtype<<<1, 32>>>((const int*)eidx, n);                     // 1
    transpose_all<<<448, 256>>>(Wd, Wt, Win, Wg1, Wg2, Wo1);         // 2
    deg_zero<<<(n + 255) / 256, 256>>>(n);                           // 3
    int nblk32 = (n + 31) / 32;
    kfeat<<<nblk32, 256, KF_SMEM>>>(des, tweet, nump, catp,          // 4 (profiled)
                                    bd, bt, bn, bc, Wn, Wc, bin, n);
    deg_count<<<(ne + 255) / 256, 256>>>(eidx, ne);                  // 5
    deg_finish<<<(n + 255) / 256, 256>>>(n);                         // 6
    scan1<<<nb, 256>>>(n);
    scan2<<<1, 128>>>(nb);
    scan3<<<nb, 256>>>(n, ne);
    csr_fill<<<(ne + 255) / 256, 256>>>(eidx, ne);

    int gather_blocks = (n * 32 + 255) / 256;

    gemm128<<<nblk32, 256>>>(0, n);
    gather<<<gather_blocks, 256>>>(bg1, n);

    gemm128<<<nblk32, 256>>>(1, n);
    gather<<<gather_blocks, 256>>>(bg2, n);

    kout<<<nblk32, 256>>>(bo1, Wo2, bo2, out, n);
}

// round 13
// speedup vs baseline: 1.1205x; 1.1205x over previous
#include <cuda_runtime.h>
#include <cuda_bf16.h>

#define NMAX 100000
#define EMAX 3300000
#define DD 128

// Static device scratch (allocation-free). 16B-aligned for vector ld/st.
__device__ __align__(16) float g_bufA[NMAX * DD];
__device__ __align__(16) float g_bufB[NMAX * DD];
__device__ __align__(16) float g_dinv[NMAX];
__device__ int   g_deg[NMAX];
__device__ int   g_fill[NMAX];
__device__ int   g_rowptr[NMAX + 1];
__device__ int   g_bsum[256];
__device__ int   g_bsum2[256];
__device__ int   g_csrsrc[EMAX];
__device__ int   g_is64;
// weights: bf16 hi/lo for des/tweet (WT[c][k]), fp32 transposed for the rest
__device__ __align__(16) __nv_bfloat16 g_WdHi[32 * 768];
__device__ __align__(16) __nv_bfloat16 g_WdLo[32 * 768];
__device__ __align__(16) __nv_bfloat16 g_WtHi[32 * 768];
__device__ __align__(16) __nv_bfloat16 g_WtLo[32 * 768];
__device__ __align__(16) float g_WinT[128 * 128];
__device__ __align__(16) float g_Wg1T[128 * 128];
__device__ __align__(16) float g_Wg2T[128 * 128];
__device__ __align__(16) float g_Wo1T[128 * 128];

__device__ __forceinline__ float lrelu(float v) { return v > 0.0f ? v : 0.01f * v; }

// packed f32x2 fma: d = a*b + d  (two independent fp32 FMAs, 2x FFMA rate)
__device__ __forceinline__ void ffma2(unsigned long long& d, unsigned long long a, unsigned long long b) {
    asm("fma.rn.f32x2 %0, %1, %2, %0;" : "+l"(d) : "l"(a), "l"(b));
}
__device__ __forceinline__ float f2sum(unsigned long long v) {
    return __int_as_float((int)(v & 0xffffffffull)) + __int_as_float((int)(v >> 32));
}
__device__ __forceinline__ unsigned long long ld64(const float* p) {
    return *(const unsigned long long*)p;
}
__device__ __forceinline__ unsigned smem_u32(const void* p) {
    unsigned a;
    asm("{ .reg .u64 t; cvta.to.shared.u64 t, %1; cvt.u32.u64 %0, t; }" : "=r"(a) : "l"(p));
    return a;
}
// pack two floats to bf16x2 (lo = a, hi = b)
__device__ __forceinline__ unsigned pack_bf16x2(float a, float b) {
    unsigned r;
    asm("cvt.rn.bf16x2.f32 %0, %1, %2;" : "=r"(r) : "f"(b), "f"(a));
    return r;
}

// Edge index fetch robust to int32-vs-int64 delivery of edge_index.
__device__ __forceinline__ int edge_at(const void* eidx, long long pos) {
    if (g_is64) return (int)(((const long long*)eidx)[pos]);
    return ((const int*)eidx)[pos];
}

__global__ void sniff_dtype(const int* __restrict__ p, int n) {
    if (threadIdx.x == 0 && blockIdx.x == 0) {
        int is64 = 1;
        for (int i = 0; i < 64; i++) {
            int lo = p[2 * i], hi = p[2 * i + 1];
            if (hi != 0 || lo < 0 || lo >= n) { is64 = 0; break; }
        }
        g_is64 = is64;
    }
}

// ---------------- weight transposes + bf16 hi/lo split ----------------
__global__ void transpose_all(
    const float* __restrict__ Wd, const float* __restrict__ Wt,
    const float* __restrict__ Win, const float* __restrict__ Wg1,
    const float* __restrict__ Wg2, const float* __restrict__ Wo1)
{
    int i = blockIdx.x * blockDim.x + threadIdx.x;
    if (i < 24576) {
        int r = i >> 5, c = i & 31;
        float v = Wd[i];
        __nv_bfloat16 h = __float2bfloat16(v);
        g_WdHi[c * 768 + r] = h;
        g_WdLo[c * 768 + r] = __float2bfloat16(v - __bfloat162float(h));
        return;
    }
    i -= 24576;
    if (i < 24576) {
        int r = i >> 5, c = i & 31;
        float v = Wt[i];
        __nv_bfloat16 h = __float2bfloat16(v);
        g_WtHi[c * 768 + r] = h;
        g_WtLo[c * 768 + r] = __float2bfloat16(v - __bfloat162float(h));
        return;
    }
    i -= 24576;
    if (i < 16384) { int r = i >> 7, c = i & 127; g_WinT[c * 128 + r] = Win[i]; return; }
    i -= 16384;
    if (i < 16384) { int r = i >> 7, c = i & 127; g_Wg1T[c * 128 + r] = Wg1[i]; return; }
    i -= 16384;
    if (i < 16384) { int r = i >> 7, c = i & 127; g_Wg2T[c * 128 + r] = Wg2[i]; return; }
    i -= 16384;
    if (i < 16384) { int r = i >> 7, c = i & 127; g_Wo1T[c * 128 + r] = Wo1[i]; return; }
}

// ---------------- degree ----------------
__global__ void deg_zero(int n) {
    int i = blockIdx.x * blockDim.x + threadIdx.x;
    if (i < n) { g_deg[i] = 0; g_fill[i] = 0; }
}
__global__ void deg_count(const void* __restrict__ eidx, int ne) {
    int e = blockIdx.x * blockDim.x + threadIdx.x;
    if (e < ne) atomicAdd(&g_deg[edge_at(eidx, (long long)ne + e)], 1);
}
__global__ void deg_finish(int n) {
    int i = blockIdx.x * blockDim.x + threadIdx.x;
    if (i < n) g_dinv[i] = rsqrtf((float)(g_deg[i] + 1));
}

// ---------------- exclusive scan of g_deg -> g_rowptr ----------------
__global__ void __launch_bounds__(256) scan1(int n) {
    __shared__ int warpsum[8];
    int t = threadIdx.x;
    int i0 = blockIdx.x * 1024 + t * 4;
    int v0 = (i0 + 0 < n) ? g_deg[i0 + 0] : 0;
    int v1 = (i0 + 1 < n) ? g_deg[i0 + 1] : 0;
    int v2 = (i0 + 2 < n) ? g_deg[i0 + 2] : 0;
    int v3 = (i0 + 3 < n) ? g_deg[i0 + 3] : 0;
    int tsum = v0 + v1 + v2 + v3;
    int x = tsum;
    #pragma unroll
    for (int o = 1; o < 32; o <<= 1) {
        int y = __shfl_up_sync(0xffffffffu, x, o);
        if ((t & 31) >= o) x += y;
    }
    if ((t & 31) == 31) warpsum[t >> 5] = x;
    __syncthreads();
    if (t < 32) {
        int w = (t < 8) ? warpsum[t] : 0;
        int xx = w;
        #pragma unroll
        for (int o = 1; o < 8; o <<= 1) {
            int y = __shfl_up_sync(0xffffffffu, xx, o);
            if (t >= o) xx += y;
        }
        if (t < 8) warpsum[t] = xx - w;
    }
    __syncthreads();
    int ex = x - tsum + warpsum[t >> 5];
    if (i0 + 0 < n) g_rowptr[i0 + 0] = ex;
    if (i0 + 1 < n) g_rowptr[i0 + 1] = ex + v0;
    if (i0 + 2 < n) g_rowptr[i0 + 2] = ex + v0 + v1;
    if (i0 + 3 < n) g_rowptr[i0 + 3] = ex + v0 + v1 + v2;
    if (t == 255) g_bsum[blockIdx.x] = ex + tsum;
}
__global__ void __launch_bounds__(128) scan2(int nb) {
    __shared__ int ws[4];
    int t = threadIdx.x;
    int v = (t < nb) ? g_bsum[t] : 0;
    int x = v;
    #pragma unroll
    for (int o = 1; o < 32; o <<= 1) {
        int y = __shfl_up_sync(0xffffffffu, x, o);
        if ((t & 31) >= o) x += y;
    }
    if ((t & 31) == 31) ws[t >> 5] = x;
    __syncthreads();
    if (t < 32) {
        int w = (t < 4) ? ws[t] : 0;
        int xx = w;
        #pragma unroll
        for (int o = 1; o < 4; o <<= 1) {
            int y = __shfl_up_sync(0xffffffffu, xx, o);
            if (t >= o) xx += y;
        }
        if (t < 4) ws[t] = xx - w;
    }
    __syncthreads();
    g_bsum2[t] = x - v + ws[t >> 5];
}
__global__ void __launch_bounds__(256) scan3(int n, int ne) {
    int t = threadIdx.x;
    int add = g_bsum2[blockIdx.x];
    int i0 = blockIdx.x * 1024 + t * 4;
    #pragma unroll
    for (int j = 0; j < 4; j++)
        if (i0 + j < n) g_rowptr[i0 + j] += add;
    if (blockIdx.x == 0 && t == 0) g_rowptr[n] = ne;
}

__global__ void csr_fill(const void* __restrict__ eidx, int ne) {
    int e = blockIdx.x * blockDim.x + threadIdx.x;
    if (e >= ne) return;
    int s = edge_at(eidx, e);
    int d = edge_at(eidx, (long long)ne + e);
    int pos = g_rowptr[d] + atomicAdd(&g_fill[d], 1);
    g_csrsrc[pos] = s;
}

// ---------------- fused feature kernel: mma.sync bf16 hi/lo phase A ----------------
// 32 nodes/block, 256 threads (8 warps = 2 m16-tiles x 4 n8-tiles).
// smem bytes: x_hi[32][200]bf16 @0 (12800), x_lo @12800, w_hi @25600, w_lo @38400,
//             x0[32][134]fp32 @51200 (17152). Total 68352 -> 3 CTAs/SM.
#define KS  200
#define X0S 134
#define KF_SMEM 68352

__global__ void __launch_bounds__(256) kfeat(
    const float* __restrict__ des, const float* __restrict__ tweet,
    const float* __restrict__ nump, const float* __restrict__ catp,
    const float* __restrict__ bd, const float* __restrict__ bt,
    const float* __restrict__ bn, const float* __restrict__ bc,
    const float* __restrict__ Wn, const float* __restrict__ Wc,
    const float* __restrict__ bin, int n)
{
    extern __shared__ char sm8[];
    unsigned smb = smem_u32(sm8);
    unsigned short* xh = (unsigned short*)sm8;
    unsigned short* xl = (unsigned short*)(sm8 + 12800);
    unsigned short* wh = (unsigned short*)(sm8 + 25600);
    unsigned short* wl = (unsigned short*)(sm8 + 38400);
    float* x0 = (float*)(sm8 + 51200);

    int t = threadIdx.x, lane = t & 31, wid = t >> 5;
    int node0 = blockIdx.x * 32;
    int m0 = (wid & 1) * 16;      // m-tile base (node within block)
    int c0 = (wid >> 1) * 8;      // n-tile base (output column)
    int g = lane >> 2, tq = lane & 3;

    // ldmatrix lane address bases (row stride 400 B)
    int ami = lane >> 3, ar = lane & 7;
    unsigned aBase = smb + ((ami < 2) ? 0u : 12800u)
                   + (unsigned)(m0 + ((ami & 1) ? 8 : 0) + ar) * 400u;
    int blane = lane & 15;
    unsigned bBase = smb + 25600u + ((blane < 8) ? 0u : 12800u)
                   + (unsigned)(c0 + (blane & 7)) * 400u;

    for (int side = 0; side < 2; side++) {
        const float* X = side ? tweet : des;
        const unsigned* WHg = side ? (const unsigned*)g_WtHi : (const unsigned*)g_WdHi;
        const unsigned* WLg = side ? (const unsigned*)g_WtLo : (const unsigned*)g_WdLo;
        float d0 = 0.f, d1 = 0.f, d2 = 0.f, d3 = 0.f;

        for (int chunk = 0; chunk < 4; chunk++) {
            int k0 = chunk * 192;
            __syncthreads();
            // stage x: 32 rows x 192 k, fp32 -> bf16 hi/lo
            for (int i2 = t; i2 < 32 * 96; i2 += 256) {
                int m = i2 / 96, q = i2 - m * 96;
                int row = min(node0 + m, n - 1);
                float2 v = ((const float2*)(X + (size_t)row * 768 + k0))[q];
                unsigned hp = pack_bf16x2(v.x, v.y);
                float hx = __bfloat162float(__ushort_as_bfloat16((unsigned short)(hp & 0xffff)));
                float hy = __bfloat162float(__ushort_as_bfloat16((unsigned short)(hp >> 16)));
                unsigned lp = pack_bf16x2(v.x - hx, v.y - hy);
                *(unsigned*)(xh + m * KS + 2 * q) = hp;
                *(unsigned*)(xl + m * KS + 2 * q) = lp;
            }
            // stage w: 32 cols x 192 k (pre-split bf16)
            for (int i2 = t; i2 < 32 * 96; i2 += 256) {
                int c = i2 / 96, q = i2 - c * 96;
                *(unsigned*)(wh + c * KS + 2 * q) = WHg[(c * 768 + k0) / 2 + q];
                *(unsigned*)(wl + c * KS + 2 * q) = WLg[(c * 768 + k0) / 2 + q];
            }
            __syncthreads();

            unsigned aaddr = aBase, baddr = bBase;
            #pragma unroll 6
            for (int s = 0; s < 24; s++) {
                unsigned a0, a1, a2, a3, b0, b1;
                asm volatile("ldmatrix.sync.aligned.m8n8.x4.shared.b16 {%0,%1,%2,%3}, [%4];"
                             : "=r"(a0), "=r"(a1), "=r"(a2), "=r"(a3) : "r"(aaddr));
                asm volatile("ldmatrix.sync.aligned.m8n8.x2.shared.b16 {%0,%1}, [%2];"
                             : "=r"(b0), "=r"(b1) : "r"(baddr));
                asm volatile("mma.sync.aligned.m16n8k8.row.col.f32.bf16.bf16.f32 "
                             "{%0,%1,%2,%3}, {%4,%5}, {%6}, {%0,%1,%2,%3};"
                             : "+f"(d0), "+f"(d1), "+f"(d2), "+f"(d3)
                             : "r"(a0), "r"(a1), "r"(b0));
                asm volatile("mma.sync.aligned.m16n8k8.row.col.f32.bf16.bf16.f32 "
                             "{%0,%1,%2,%3}, {%4,%5}, {%6}, {%0,%1,%2,%3};"
                             : "+f"(d0), "+f"(d1), "+f"(d2), "+f"(d3)
                             : "r"(a0), "r"(a1), "r"(b1));
                asm volatile("mma.sync.aligned.m16n8k8.row.col.f32.bf16.bf16.f32 "
                             "{%0,%1,%2,%3}, {%4,%5}, {%6}, {%0,%1,%2,%3};"
                             : "+f"(d0), "+f"(d1), "+f"(d2), "+f"(d3)
                             : "r"(a2), "r"(a3), "r"(b0));
                aaddr += 16;
                baddr += 16;
            }
        }
        // writeback D -> x0 (bias + lrelu). Thread holds D[g][2tq..], D[g+8][2tq..].
        const float* bias = side ? bt : bd;
        int cc = c0 + 2 * tq;
        float b0f = bias[cc], b1f = bias[cc + 1];
        x0[(m0 + g) * X0S + side * 32 + cc]         = lrelu(d0 + b0f);
        x0[(m0 + g) * X0S + side * 32 + cc + 1]     = lrelu(d1 + b1f);
        x0[(m0 + g + 8) * X0S + side * 32 + cc]     = lrelu(d2 + b0f);
        x0[(m0 + g + 8) * X0S + side * 32 + cc + 1] = lrelu(d3 + b1f);
    }

    // num/cat features: cols 64..127
    for (int o = t; o < 32 * 64; o += 256) {
        int m = o >> 6, c = o & 63;
        int row = min(node0 + m, n - 1);
        float v;
        if (c < 32) {
            v = bn[c];
            const float* xp = nump + (size_t)row * 6;
            #pragma unroll
            for (int k = 0; k < 6; k++) v += xp[k] * Wn[k * 32 + c];
        } else {
            int cc2 = c - 32;
            v = bc[cc2];
            const float* xp = catp + (size_t)row * 11;
            #pragma unroll
            for (int k = 0; k < 11; k++) v += xp[k] * Wc[k * 32 + cc2];
        }
        x0[m * X0S + 64 + c] = lrelu(v);
    }
    __syncthreads();

    // phase B: x1 = lrelu(x0 @ Win + bin) -> g_bufA (f32x2)
    {
        int cg2 = t >> 3, ng2 = t & 7;
        int cb0 = cg2 * 4;
        unsigned long long acc[4][4];
        #pragma unroll
        for (int i = 0; i < 4; i++)
            #pragma unroll
            for (int j = 0; j < 4; j++) acc[i][j] = 0;

        #pragma unroll 4
        for (int kk = 0; kk < 64; kk++) {
            int k = 2 * kk;
            unsigned long long x2[4];
            #pragma unroll
            for (int j = 0; j < 4; j++) x2[j] = ld64(x0 + (ng2 + 8 * j) * X0S + k);
            #pragma unroll
            for (int i = 0; i < 4; i++) {
                unsigned long long w2 = ld64(g_WinT + (cb0 + i) * 128 + k);
                #pragma unroll
                for (int j = 0; j < 4; j++) ffma2(acc[i][j], x2[j], w2);
            }
        }
        #pragma unroll
        for (int i = 0; i < 4; i++) {
            float b = bin[cb0 + i];
            #pragma unroll
            for (int j = 0; j < 4; j++) {
                int node = node0 + ng2 + 8 * j;
                if (node < n)
                    g_bufA[(size_t)node * 128 + cb0 + i] = lrelu(f2sum(acc[i][j]) + b);
            }
        }
    }
}

// ---------------- 128x128 GEMM (f32x2): g_bufA @ W -> g_bufB, 32 nodes/block ----------------
__global__ void __launch_bounds__(256) gemm128(int sel, int n)
{
    __shared__ float xs[32 * X0S];
    const float* WT = sel ? g_Wg2T : g_Wg1T;
    int t = threadIdx.x;
    int node0 = blockIdx.x * 32;

    for (int i = t; i < 32 * 64; i += 256) {
        int m = i >> 6, q = i & 63;
        int row = min(node0 + m, n - 1);
        float2 v = ((const float2*)(g_bufA + (size_t)row * 128))[q];
        *(float2*)(xs + m * X0S + 2 * q) = v;
    }
    __syncthreads();

    int cg = t >> 3;
    int ng = t & 7;
    int c0 = cg * 4;
    unsigned long long acc[4][4];
    #pragma unroll
    for (int i = 0; i < 4; i++)
        #pragma unroll
        for (int j = 0; j < 4; j++) acc[i][j] = 0;

    #pragma unroll 4
    for (int kk = 0; kk < 64; kk++) {
        int k = 2 * kk;
        unsigned long long x2[4];
        #pragma unroll
        for (int j = 0; j < 4; j++) x2[j] = ld64(xs + (ng + 8 * j) * X0S + k);
        #pragma unroll
        for (int i = 0; i < 4; i++) {
            unsigned long long w2 = ld64(WT + (c0 + i) * 128 + k);
            #pragma unroll
            for (int j = 0; j < 4; j++) ffma2(acc[i][j], x2[j], w2);
        }
    }
    #pragma unroll
    for (int i = 0; i < 4; i++)
        #pragma unroll
        for (int j = 0; j < 4; j++) {
            int node = node0 + ng + 8 * j;
            if (node < n)
                g_bufB[(size_t)node * 128 + c0 + i] = f2sum(acc[i][j]);
        }
}

// ---------------- CSR gather aggregation (fused self-loop + bias) ----------------
__global__ void __launch_bounds__(256) gather(const float* __restrict__ bias, int n)
{
    int gid = blockIdx.x * blockDim.x + threadIdx.x;
    int node = gid >> 5;
    int lane = gid & 31;
    if (node >= n) return;

    const float4* Y4 = (const float4*)g_bufB;
    float wd = g_dinv[node];
    float4 y = Y4[(size_t)node * 32 + lane];
    float4 acc, acc2;
    acc.x = wd * y.x; acc.y = wd * y.y; acc.z = wd * y.z; acc.w = wd * y.w;
    acc2.x = 0.f; acc2.y = 0.f; acc2.z = 0.f; acc2.w = 0.f;

    int lo = g_rowptr[node], hi = g_rowptr[node + 1];
    int e = lo;
    for (; e + 2 <= hi; e += 2) {
        int s0 = g_csrsrc[e], s1 = g_csrsrc[e + 1];
        float w0 = g_dinv[s0], w1 = g_dinv[s1];
        float4 a4 = Y4[(size_t)s0 * 32 + lane];
        float4 b4 = Y4[(size_t)s1 * 32 + lane];
        acc.x += w0 * a4.x; acc.y += w0 * a4.y; acc.z += w0 * a4.z; acc.w += w0 * a4.w;
        acc2.x += w1 * b4.x; acc2.y += w1 * b4.y; acc2.z += w1 * b4.z; acc2.w += w1 * b4.w;
    }
    if (e < hi) {
        int s = g_csrsrc[e];
        float w = g_dinv[s];
        float4 ys = Y4[(size_t)s * 32 + lane];
        acc.x += w * ys.x; acc.y += w * ys.y; acc.z += w * ys.z; acc.w += w * ys.w;
    }
    acc.x += acc2.x; acc.y += acc2.y; acc.z += acc2.z; acc.w += acc2.w;

    float4 b4 = ((const float4*)bias)[lane];
    float4 o;
    o.x = wd * acc.x + b4.x; o.y = wd * acc.y + b4.y;
    o.z = wd * acc.z + b4.z; o.w = wd * acc.w + b4.w;
    ((float4*)g_bufA)[(size_t)node * 32 + lane] = o;
}

// ---------------- output head (f32x2 phase1): 32 nodes/block ----------------
__global__ void __launch_bounds__(256) kout(
    const float* __restrict__ bo1,
    const float* __restrict__ Wo2, const float* __restrict__ bo2,
    float* __restrict__ out, int n)
{
    __shared__ float xs[32 * X0S];
    __shared__ float sa[32 * X0S];
    int t = threadIdx.x;
    int node0 = blockIdx.x * 32;

    for (int i = t; i < 32 * 64; i += 256) {
        int m = i >> 6, q = i & 63;
        int row = min(node0 + m, n - 1);
        float2 v = ((const float2*)(g_bufA + (size_t)row * 128))[q];
        *(float2*)(xs + m * X0S + 2 * q) = v;
    }
    __syncthreads();

    int cg = t >> 3;
    int ng = t & 7;
    int c0 = cg * 4;
    unsigned long long acc[4][4];
    #pragma unroll
    for (int i = 0; i < 4; i++)
        #pragma unroll
        for (int j = 0; j < 4; j++) acc[i][j] = 0;

    #pragma unroll 4
    for (int kk = 0; kk < 64; kk++) {
        int k = 2 * kk;
        unsigned long long x2[4];
        #pragma unroll
        for (int j = 0; j < 4; j++) x2[j] = ld64(xs + (ng + 8 * j) * X0S + k);
        #pragma unroll
        for (int i = 0; i < 4; i++) {
            unsigned long long w2 = ld64(g_Wo1T + (c0 + i) * 128 + k);
            #pragma unroll
            for (int j = 0; j < 4; j++) ffma2(acc[i][j], x2[j], w2);
        }
    }
    #pragma unroll
    for (int i = 0; i < 4; i++) {
        float b = bo1[c0 + i];
        #pragma unroll
        for (int j = 0; j < 4; j++)
            sa[(ng + 8 * j) * X0S + c0 + i] = lrelu(f2sum(acc[i][j]) + b);
    }
    __syncthreads();

    if (t < 64) {
        int m = t >> 1, c = t & 1;
        float s = bo2[c];
        const float* row = sa + m * X0S;
        #pragma unroll 4
        for (int k = 0; k < 128; k++) s += row[k] * Wo2[k * 2 + c];
        int node = node0 + m;
        if (node < n) out[(size_t)node * 2 + c] = s;
    }
}

extern "C" void kernel_launch(void* const* d_in, const int* in_sizes, int n_in,
                              void* d_out, int out_size)
{
    const float* des   = (const float*)d_in[0];
    const float* tweet = (const float*)d_in[1];
    const float* nump  = (const float*)d_in[2];
    const float* catp  = (const float*)d_in[3];
    const void*  eidx  = d_in[4];
    const float* Wd  = (const float*)d_in[6];  const float* bd  = (const float*)d_in[7];
    const float* Wt  = (const float*)d_in[8];  const float* bt  = (const float*)d_in[9];
    const float* Wn  = (const float*)d_in[10]; const float* bn  = (const float*)d_in[11];
    const float* Wc  = (const float*)d_in[12]; const float* bc  = (const float*)d_in[13];
    const float* Win = (const float*)d_in[14]; const float* bin = (const float*)d_in[15];
    const float* Wg1 = (const float*)d_in[16]; const float* bg1 = (const float*)d_in[17];
    const float* Wg2 = (const float*)d_in[18]; const float* bg2 = (const float*)d_in[19];
    const float* Wo1 = (const float*)d_in[20]; const float* bo1 = (const float*)d_in[21];
    const float* Wo2 = (const float*)d_in[22]; const float* bo2 = (const float*)d_in[23];
    float* out = (float*)d_out;

    int n  = in_sizes[2] / 6;
    int ne = in_sizes[5];
    int nb = (n + 1023) / 1024;

    cudaFuncSetAttribute(kfeat, cudaFuncAttributeMaxDynamicSharedMemorySize, KF_SMEM);

    // kfeat stays at launch slot #4 (the profiled launch).
    sniff_dtype<<<1, 32>>>((const int*)eidx, n);                     // 1
    transpose_all<<<448, 256>>>(Wd, Wt, Win, Wg1, Wg2, Wo1);         // 2
    deg_zero<<<(n + 255) / 256, 256>>>(n);                           // 3
    int nblk32 = (n + 31) / 32;
    kfeat<<<nblk32, 256, KF_SMEM>>>(des, tweet, nump, catp,          // 4 (profiled)
                                    bd, bt, bn, bc, Wn, Wc, bin, n);
    deg_count<<<(ne + 255) / 256, 256>>>(eidx, ne);                  // 5
    deg_finish<<<(n + 255) / 256, 256>>>(n);                         // 6
    scan1<<<nb, 256>>>(n);
    scan2<<<1, 128>>>(nb);
    scan3<<<nb, 256>>>(n, ne);
    csr_fill<<<(ne + 255) / 256, 256>>>(eidx, ne);

    int gather_blocks = (n * 32 + 255) / 256;

    gemm128<<<nblk32, 256>>>(0, n);
    gather<<<gather_blocks, 256>>>(bg1, n);

    gemm128<<<nblk32, 256>>>(1, n);
    gather<<<gather_blocks, 256>>>(bg2, n);

    kout<<<nblk32, 256>>>(bo1, Wo2, bo2, out, n);
}